// round 2
// baseline (speedup 1.0000x reference)
#include <cuda_runtime.h>

#define NMAX 100000
#define DD 128

// Scratch (static device arrays; allocation is forbidden)
__device__ float g_side[(size_t)NMAX * DD];
__device__ float g_S[(size_t)NMAX * DD];
__device__ float g_P[(size_t)NMAX * DD];
__device__ float g_ego[(size_t)NMAX * DD];

__global__ __launch_bounds__(256) void copy_kernel(const float* __restrict__ src,
                                                   float* __restrict__ dst, int n4) {
    int i = blockIdx.x * blockDim.x + threadIdx.x;
    if (i < n4) ((float4*)dst)[i] = ((const float4*)src)[i];
}

__global__ __launch_bounds__(256) void zero_side_kernel(int n4) {
    int i = blockIdx.x * blockDim.x + threadIdx.x;
    if (i < n4) ((float4*)g_side)[i] = make_float4(0.f, 0.f, 0.f, 0.f);
}

// One warp per edge: gather src row (512B), scale, scatter-add to dst row.
__global__ __launch_bounds__(256) void spmm_kernel(const float* __restrict__ x,
                                                   const int* __restrict__ src,
                                                   const int* __restrict__ dst,
                                                   const float* __restrict__ val,
                                                   int E) {
    int warp = (blockIdx.x * blockDim.x + threadIdx.x) >> 5;
    int lane = threadIdx.x & 31;
    if (warp >= E) return;
    int s = __ldg(src + warp);
    int d = __ldg(dst + warp);
    float v = __ldg(val + warp);
    float4 m = ((const float4*)(x + (size_t)s * DD))[lane];
    float* o = g_side + (size_t)d * DD + lane * 4;
    atomicAdd(o + 0, v * m.x);
    atomicAdd(o + 1, v * m.y);
    atomicAdd(o + 2, v * m.z);
    atomicAdd(o + 3, v * m.w);
}

// Tiled SGEMM: OUT[n][j] = sum_k A[n][k] * W[k][j]
// A = ego + side (mode 0, -> g_S) or ego * side (mode 1, -> g_P)
// ego source: use_g_ego ? g_ego : emb  (chosen in-kernel; no host API calls)
// BM=128, BN=128 (= full D), BK=8, 256 threads, 8x8 register tile.
__global__ __launch_bounds__(256) void gemm_kernel(const float* __restrict__ emb,
                                                   int use_g_ego,
                                                   const float* __restrict__ W_sum,
                                                   const float* __restrict__ W_prod,
                                                   int n_rows) {
    __shared__ float As[8][128];   // A^T tile
    __shared__ float Bs[8][128];

    const float* __restrict__ ego = use_g_ego ? (const float*)g_ego : emb;

    const int mode = blockIdx.y;
    const float* __restrict__ W = mode ? W_prod : W_sum;
    float* __restrict__ OUT = mode ? g_P : g_S;

    const int tid = threadIdx.x;
    const int tx = tid & 15;        // 16 col-groups x 8
    const int ty = tid >> 4;        // 16 row-groups x 8
    const int row0 = blockIdx.x * 128;

    // A tile load mapping: 128 rows x 8 cols -> 256 float4 loads
    const int a_row = tid & 127;
    const int a_coff = (tid >> 7) * 4;
    // B tile load mapping: 8 rows x 128 cols
    const int b_row = tid >> 5;
    const int b_col = (tid & 31) * 4;

    const int g_row = row0 + a_row;
    const bool a_ok = g_row < n_rows;
    const float* ep = ego + (size_t)g_row * DD + a_coff;
    const float* sp = g_side + (size_t)g_row * DD + a_coff;

    float acc[8][8];
#pragma unroll
    for (int i = 0; i < 8; i++)
#pragma unroll
        for (int j = 0; j < 8; j++) acc[i][j] = 0.f;

    for (int k0 = 0; k0 < DD; k0 += 8) {
        float4 e4 = make_float4(0.f, 0.f, 0.f, 0.f);
        float4 s4 = e4;
        if (a_ok) {
            e4 = *(const float4*)(ep + k0);
            s4 = *(const float4*)(sp + k0);
        }
        float4 a4;
        if (mode) {
            a4.x = e4.x * s4.x; a4.y = e4.y * s4.y;
            a4.z = e4.z * s4.z; a4.w = e4.w * s4.w;
        } else {
            a4.x = e4.x + s4.x; a4.y = e4.y + s4.y;
            a4.z = e4.z + s4.z; a4.w = e4.w + s4.w;
        }
        As[a_coff + 0][a_row] = a4.x;
        As[a_coff + 1][a_row] = a4.y;
        As[a_coff + 2][a_row] = a4.z;
        As[a_coff + 3][a_row] = a4.w;
        *(float4*)&Bs[b_row][b_col] =
            *(const float4*)(W + (size_t)(k0 + b_row) * DD + b_col);
        __syncthreads();
#pragma unroll
        for (int k = 0; k < 8; k++) {
            float a[8], b[8];
            *(float4*)&a[0] = *(const float4*)&As[k][ty * 8];
            *(float4*)&a[4] = *(const float4*)&As[k][ty * 8 + 4];
            *(float4*)&b[0] = *(const float4*)&Bs[k][tx * 8];
            *(float4*)&b[4] = *(const float4*)&Bs[k][tx * 8 + 4];
#pragma unroll
            for (int i = 0; i < 8; i++)
#pragma unroll
                for (int j = 0; j < 8; j++) acc[i][j] += a[i] * b[j];
        }
        __syncthreads();
    }

#pragma unroll
    for (int i = 0; i < 8; i++) {
        int r = row0 + ty * 8 + i;
        if (r < n_rows) {
            float4 o;
            o.x = acc[i][0]; o.y = acc[i][1]; o.z = acc[i][2]; o.w = acc[i][3];
            *(float4*)(OUT + (size_t)r * DD + tx * 8) = o;
            o.x = acc[i][4]; o.y = acc[i][5]; o.z = acc[i][6]; o.w = acc[i][7];
            *(float4*)(OUT + (size_t)r * DD + tx * 8 + 4) = o;
        }
    }
}

__device__ __forceinline__ float lrelu(float x) {
    return x > 0.f ? x : 0.01f * x;
}

// ego = lrelu(S + b_s) + lrelu(P + b_p); out = ego / max(||ego||, 1e-12)
// One warp per row. Writes un-normalized ego to g_ego for the next layer.
__global__ __launch_bounds__(256) void combine_norm_kernel(const float* __restrict__ bs,
                                                           const float* __restrict__ bp,
                                                           float* __restrict__ out_norm,
                                                           int n_rows) {
    int warp = (blockIdx.x * blockDim.x + threadIdx.x) >> 5;
    int lane = threadIdx.x & 31;
    if (warp >= n_rows) return;
    size_t off = (size_t)warp * DD + lane * 4;
    float4 s = *(const float4*)(g_S + off);
    float4 p = *(const float4*)(g_P + off);
    float4 b1 = *(const float4*)(bs + lane * 4);
    float4 b2 = *(const float4*)(bp + lane * 4);
    float4 e;
    e.x = lrelu(s.x + b1.x) + lrelu(p.x + b2.x);
    e.y = lrelu(s.y + b1.y) + lrelu(p.y + b2.y);
    e.z = lrelu(s.z + b1.z) + lrelu(p.z + b2.z);
    e.w = lrelu(s.w + b1.w) + lrelu(p.w + b2.w);
    float ss = e.x * e.x + e.y * e.y + e.z * e.z + e.w * e.w;
#pragma unroll
    for (int o = 16; o; o >>= 1) ss += __shfl_xor_sync(0xffffffffu, ss, o);
    float inv = 1.f / fmaxf(sqrtf(ss), 1e-12f);
    *(float4*)(g_ego + off) = e;
    float4 en;
    en.x = e.x * inv; en.y = e.y * inv; en.z = e.z * inv; en.w = e.w * inv;
    *(float4*)(out_norm + off) = en;
}

extern "C" void kernel_launch(void* const* d_in, const int* in_sizes, int n_in,
                              void* d_out, int out_size) {
    const float* emb    = (const float*)d_in[0];
    const int*   e_src  = (const int*)d_in[1];
    const int*   e_dst  = (const int*)d_in[2];
    const float* e_val  = (const float*)d_in[3];
    const float* W_sum  = (const float*)d_in[4];
    const float* b_sum  = (const float*)d_in[5];
    const float* W_prod = (const float*)d_in[6];
    const float* b_prod = (const float*)d_in[7];
    float* out = (float*)d_out;

    const int N = in_sizes[0] / DD;
    const int E = in_sizes[1];
    const int L = in_sizes[4] / (DD * DD);

    const int n4 = N * (DD / 4);
    const int eb_blocks = (n4 + 255) / 256;

    // out[0] = embeddings
    copy_kernel<<<eb_blocks, 256>>>(emb, out, n4);

    const int spmm_blocks = (E + 7) / 8;          // 8 warps/block, 1 warp/edge
    const int gemm_bx = (N + 127) / 128;
    const int cn_blocks = (N + 7) / 8;            // 8 warps/block, 1 warp/row

    for (int i = 0; i < L; i++) {
        const float* x = out + (size_t)i * N * DD;   // normalized prev layer
        zero_side_kernel<<<eb_blocks, 256>>>(n4);
        spmm_kernel<<<spmm_blocks, 256>>>(x, e_src, e_dst, e_val, E);
        gemm_kernel<<<dim3(gemm_bx, 2), 256>>>(emb, (i == 0) ? 0 : 1,
                                               W_sum + (size_t)i * DD * DD,
                                               W_prod + (size_t)i * DD * DD, N);
        combine_norm_kernel<<<cn_blocks, 256>>>(b_sum + (size_t)i * DD,
                                                b_prod + (size_t)i * DD,
                                                out + (size_t)(i + 1) * N * DD, N);
    }
}

// round 6
// speedup vs baseline: 1.5311x; 1.5311x over previous
#include <cuda_runtime.h>

#define NMAX 100000
#define DD 128

// Scratch (static device arrays; allocation is forbidden)
__device__ float g_side[(size_t)NMAX * DD];
__device__ float g_S[(size_t)NMAX * DD];
__device__ float g_P[(size_t)NMAX * DD];
__device__ float g_ego[(size_t)NMAX * DD];

__global__ __launch_bounds__(256) void copy_kernel(const float* __restrict__ src,
                                                   float* __restrict__ dst, int n4) {
    int i = blockIdx.x * blockDim.x + threadIdx.x;
    if (i < n4) ((float4*)dst)[i] = ((const float4*)src)[i];
}

__global__ __launch_bounds__(256) void zero_side_kernel(int n4) {
    int i = blockIdx.x * blockDim.x + threadIdx.x;
    if (i < n4) ((float4*)g_side)[i] = make_float4(0.f, 0.f, 0.f, 0.f);
}

// One warp per edge: gather src row (512B), scale, scatter-add to dst row
// using vector reductions (red.global.add.v4.f32, sm_90+): 1 RED per lane
// instead of 4 -> 4x fewer atomic ops.
__global__ __launch_bounds__(256) void spmm_kernel(const float* __restrict__ x,
                                                   const int* __restrict__ src,
                                                   const int* __restrict__ dst,
                                                   const float* __restrict__ val,
                                                   int E) {
    int warp = (blockIdx.x * blockDim.x + threadIdx.x) >> 5;
    int lane = threadIdx.x & 31;
    if (warp >= E) return;
    int s = __ldg(src + warp);
    int d = __ldg(dst + warp);
    float v = __ldg(val + warp);
    float4 m = ((const float4*)(x + (size_t)s * DD))[lane];
    float* o = g_side + (size_t)d * DD + lane * 4;
    asm volatile("red.global.add.v4.f32 [%0], {%1, %2, %3, %4};"
                 :: "l"(o), "f"(v * m.x), "f"(v * m.y), "f"(v * m.z), "f"(v * m.w)
                 : "memory");
}

// Tiled SGEMM: OUT[n][j] = sum_k A[n][k] * W[k][j]
// A = ego + side (mode 0, -> g_S) or ego * side (mode 1, -> g_P)
// ego source: use_g_ego ? g_ego : emb  (chosen in-kernel; no host API calls)
// BM=128, BN=128 (= full D), BK=8, 256 threads, 8x8 register tile.
__global__ __launch_bounds__(256) void gemm_kernel(const float* __restrict__ emb,
                                                   int use_g_ego,
                                                   const float* __restrict__ W_sum,
                                                   const float* __restrict__ W_prod,
                                                   int n_rows) {
    __shared__ float As[8][128];   // A^T tile
    __shared__ float Bs[8][128];

    const float* __restrict__ ego = use_g_ego ? (const float*)g_ego : emb;

    const int mode = blockIdx.y;
    const float* __restrict__ W = mode ? W_prod : W_sum;
    float* __restrict__ OUT = mode ? g_P : g_S;

    const int tid = threadIdx.x;
    const int tx = tid & 15;        // 16 col-groups x 8
    const int ty = tid >> 4;        // 16 row-groups x 8
    const int row0 = blockIdx.x * 128;

    // A tile load mapping: 128 rows x 8 cols -> 256 float4 loads
    const int a_row = tid & 127;
    const int a_coff = (tid >> 7) * 4;
    // B tile load mapping: 8 rows x 128 cols
    const int b_row = tid >> 5;
    const int b_col = (tid & 31) * 4;

    const int g_row = row0 + a_row;
    const bool a_ok = g_row < n_rows;
    const float* ep = ego + (size_t)g_row * DD + a_coff;
    const float* sp = g_side + (size_t)g_row * DD + a_coff;

    float acc[8][8];
#pragma unroll
    for (int i = 0; i < 8; i++)
#pragma unroll
        for (int j = 0; j < 8; j++) acc[i][j] = 0.f;

    for (int k0 = 0; k0 < DD; k0 += 8) {
        float4 e4 = make_float4(0.f, 0.f, 0.f, 0.f);
        float4 s4 = e4;
        if (a_ok) {
            e4 = *(const float4*)(ep + k0);
            s4 = *(const float4*)(sp + k0);
        }
        float4 a4;
        if (mode) {
            a4.x = e4.x * s4.x; a4.y = e4.y * s4.y;
            a4.z = e4.z * s4.z; a4.w = e4.w * s4.w;
        } else {
            a4.x = e4.x + s4.x; a4.y = e4.y + s4.y;
            a4.z = e4.z + s4.z; a4.w = e4.w + s4.w;
        }
        As[a_coff + 0][a_row] = a4.x;
        As[a_coff + 1][a_row] = a4.y;
        As[a_coff + 2][a_row] = a4.z;
        As[a_coff + 3][a_row] = a4.w;
        *(float4*)&Bs[b_row][b_col] =
            *(const float4*)(W + (size_t)(k0 + b_row) * DD + b_col);
        __syncthreads();
#pragma unroll
        for (int k = 0; k < 8; k++) {
            float a[8], b[8];
            *(float4*)&a[0] = *(const float4*)&As[k][ty * 8];
            *(float4*)&a[4] = *(const float4*)&As[k][ty * 8 + 4];
            *(float4*)&b[0] = *(const float4*)&Bs[k][tx * 8];
            *(float4*)&b[4] = *(const float4*)&Bs[k][tx * 8 + 4];
#pragma unroll
            for (int i = 0; i < 8; i++)
#pragma unroll
                for (int j = 0; j < 8; j++) acc[i][j] += a[i] * b[j];
        }
        __syncthreads();
    }

#pragma unroll
    for (int i = 0; i < 8; i++) {
        int r = row0 + ty * 8 + i;
        if (r < n_rows) {
            float4 o;
            o.x = acc[i][0]; o.y = acc[i][1]; o.z = acc[i][2]; o.w = acc[i][3];
            *(float4*)(OUT + (size_t)r * DD + tx * 8) = o;
            o.x = acc[i][4]; o.y = acc[i][5]; o.z = acc[i][6]; o.w = acc[i][7];
            *(float4*)(OUT + (size_t)r * DD + tx * 8 + 4) = o;
        }
    }
}

__device__ __forceinline__ float lrelu(float x) {
    return x > 0.f ? x : 0.01f * x;
}

// ego = lrelu(S + b_s) + lrelu(P + b_p); out = ego / max(||ego||, 1e-12)
// One warp per row. Writes un-normalized ego to g_ego for the next layer.
__global__ __launch_bounds__(256) void combine_norm_kernel(const float* __restrict__ bs,
                                                           const float* __restrict__ bp,
                                                           float* __restrict__ out_norm,
                                                           int n_rows) {
    int warp = (blockIdx.x * blockDim.x + threadIdx.x) >> 5;
    int lane = threadIdx.x & 31;
    if (warp >= n_rows) return;
    size_t off = (size_t)warp * DD + lane * 4;
    float4 s = *(const float4*)(g_S + off);
    float4 p = *(const float4*)(g_P + off);
    float4 b1 = *(const float4*)(bs + lane * 4);
    float4 b2 = *(const float4*)(bp + lane * 4);
    float4 e;
    e.x = lrelu(s.x + b1.x) + lrelu(p.x + b2.x);
    e.y = lrelu(s.y + b1.y) + lrelu(p.y + b2.y);
    e.z = lrelu(s.z + b1.z) + lrelu(p.z + b2.z);
    e.w = lrelu(s.w + b1.w) + lrelu(p.w + b2.w);
    float ss = e.x * e.x + e.y * e.y + e.z * e.z + e.w * e.w;
#pragma unroll
    for (int o = 16; o; o >>= 1) ss += __shfl_xor_sync(0xffffffffu, ss, o);
    float inv = 1.f / fmaxf(sqrtf(ss), 1e-12f);
    *(float4*)(g_ego + off) = e;
    float4 en;
    en.x = e.x * inv; en.y = e.y * inv; en.z = e.z * inv; en.w = e.w * inv;
    *(float4*)(out_norm + off) = en;
}

extern "C" void kernel_launch(void* const* d_in, const int* in_sizes, int n_in,
                              void* d_out, int out_size) {
    const float* emb    = (const float*)d_in[0];
    const int*   e_src  = (const int*)d_in[1];
    const int*   e_dst  = (const int*)d_in[2];
    const float* e_val  = (const float*)d_in[3];
    const float* W_sum  = (const float*)d_in[4];
    const float* b_sum  = (const float*)d_in[5];
    const float* W_prod = (const float*)d_in[6];
    const float* b_prod = (const float*)d_in[7];
    float* out = (float*)d_out;

    const int N = in_sizes[0] / DD;
    const int E = in_sizes[1];
    const int L = in_sizes[4] / (DD * DD);

    const int n4 = N * (DD / 4);
    const int eb_blocks = (n4 + 255) / 256;

    // out[0] = embeddings
    copy_kernel<<<eb_blocks, 256>>>(emb, out, n4);

    const int spmm_blocks = (E + 7) / 8;          // 8 warps/block, 1 warp/edge
    const int gemm_bx = (N + 127) / 128;
    const int cn_blocks = (N + 7) / 8;            // 8 warps/block, 1 warp/row

    for (int i = 0; i < L; i++) {
        const float* x = out + (size_t)i * N * DD;   // normalized prev layer
        zero_side_kernel<<<eb_blocks, 256>>>(n4);
        spmm_kernel<<<spmm_blocks, 256>>>(x, e_src, e_dst, e_val, E);
        gemm_kernel<<<dim3(gemm_bx, 2), 256>>>(emb, (i == 0) ? 0 : 1,
                                               W_sum + (size_t)i * DD * DD,
                                               W_prod + (size_t)i * DD * DD, N);
        combine_norm_kernel<<<cn_blocks, 256>>>(b_sum + (size_t)i * DD,
                                                b_prod + (size_t)i * DD,
                                                out + (size_t)(i + 1) * N * DD, N);
    }
}

// round 8
// speedup vs baseline: 1.5371x; 1.0039x over previous
#include <cuda_runtime.h>
#include <cstdint>

#define NMAX 100000
#define DD 128

// Scratch (static device arrays; allocation is forbidden)
__device__ float g_side[(size_t)NMAX * DD];
__device__ float g_S[(size_t)NMAX * DD];
__device__ float g_P[(size_t)NMAX * DD];
__device__ float g_ego[(size_t)NMAX * DD];

__global__ __launch_bounds__(256) void copy_kernel(const float* __restrict__ src,
                                                   float* __restrict__ dst, int n4) {
    int i = blockIdx.x * blockDim.x + threadIdx.x;
    if (i < n4) ((float4*)dst)[i] = ((const float4*)src)[i];
}

__global__ __launch_bounds__(256) void zero_side_kernel(int n4) {
    int i = blockIdx.x * blockDim.x + threadIdx.x;
    if (i < n4) ((float4*)g_side)[i] = make_float4(0.f, 0.f, 0.f, 0.f);
}

// One warp per edge: gather src row, scale, v4-RED scatter-add to dst row.
__global__ __launch_bounds__(256) void spmm_kernel(const float* __restrict__ x,
                                                   const int* __restrict__ src,
                                                   const int* __restrict__ dst,
                                                   const float* __restrict__ val,
                                                   int E) {
    int warp = (blockIdx.x * blockDim.x + threadIdx.x) >> 5;
    int lane = threadIdx.x & 31;
    if (warp >= E) return;
    int s = __ldg(src + warp);
    int d = __ldg(dst + warp);
    float v = __ldg(val + warp);
    float4 m = ((const float4*)(x + (size_t)s * DD))[lane];
    float* o = g_side + (size_t)d * DD + lane * 4;
    asm volatile("red.global.add.v4.f32 [%0], {%1, %2, %3, %4};"
                 :: "l"(o), "f"(v * m.x), "f"(v * m.y), "f"(v * m.z), "f"(v * m.w)
                 : "memory");
}

// ---------------- tf32 mma.sync GEMM --------------------------------------
// OUT[n][j] = sum_k A[n][k] * W[k][j];  A = ego+side (mode 0 -> g_S) or
// ego*side (mode 1 -> g_P). 128x128x128 per CTA, 256 threads, 8 warps (4m x 2n),
// warp tile 32x64, mma.sync.m16n8k8 tf32 (baseline PTX -> HMMA on sm_103).
//
// SMEM fragment-packed layouts:
//  Af: per (m_block 0..7, s 0..15) block of 136 words: lane*4 + reg
//      reg order = {A[g][tg], A[g+8][tg], A[g][tg+4], A[g+8][tg+4]} (m16n8k8 A frag)
//  Bf: per (n_block 0..15, s 0..15) block of 64 words: lane*2 + reg
//      reg order = {B[tg][g], B[tg+4][g]} (B frag, B = W k x n)
#define A_BLK 136                       // words per (mb,s) block (pad 8 words)
#define AF_WORDS (8 * 16 * A_BLK)       // 17408 words
#define BF_WORDS (16 * 16 * 64)         // 16384 words
#define GEMM_SMEM ((AF_WORDS + BF_WORDS) * 4)

__device__ __forceinline__ uint32_t to_tf32(float f) {
    uint32_t u;
    asm("cvt.rna.tf32.f32 %0, %1;" : "=r"(u) : "f"(f));
    return u;
}

__global__ __launch_bounds__(256, 1) void gemm_mma_kernel(const float* __restrict__ emb,
                                                          int use_g_ego,
                                                          const float* __restrict__ W_sum,
                                                          const float* __restrict__ W_prod,
                                                          int n_rows) {
    extern __shared__ uint32_t smem[];
    uint32_t* Af = smem;
    uint32_t* Bf = smem + AF_WORDS;

    const int tid = threadIdx.x;
    const int wid = tid >> 5;
    const int lane = tid & 31;
    const int mode = blockIdx.y;
    const int row0 = blockIdx.x * 128;

    const float* __restrict__ ego = use_g_ego ? (const float*)g_ego : emb;
    const float* __restrict__ W = mode ? W_prod : W_sum;
    float* __restrict__ OUT = mode ? g_P : g_S;

    // ---- fill A fragments (coalesced reads: warp lanes span 32 consecutive cols)
    for (int i = tid; i < 16384; i += 256) {
        int row = i >> 7, col = i & 127;
        int gr = row0 + row;
        float a = 0.f;
        if (gr < n_rows) {
            float e = __ldg(ego + (size_t)gr * DD + col);
            float sd = __ldg(g_side + (size_t)gr * DD + col);
            a = mode ? e * sd : e + sd;
        }
        int mb = row >> 4, r = row & 15, g = r & 7, hi = r >> 3;
        int s = col >> 3, c = col & 7, tg = c & 3, chi = c >> 2;
        Af[(mb * 16 + s) * A_BLK + (g * 4 + tg) * 4 + hi + 2 * chi] = to_tf32(a);
    }

    // ---- fill B fragments. i decomposed so STS is ~2-way-conflict max.
    for (int i = tid; i < 16384; i += 256) {
        int l32 = i & 31;                 // = g*4+tg
        int g = l32 >> 2, tg = l32 & 3;
        int rest = i >> 5;
        int hi = rest & 1, s = (rest >> 1) & 15, nb = rest >> 5;
        int k = s * 8 + hi * 4 + tg;
        int n = nb * 8 + g;
        Bf[(nb * 16 + s) * 64 + l32 * 2 + hi] = to_tf32(__ldg(W + (size_t)k * DD + n));
    }
    __syncthreads();

    // ---- compute: warp tile 32(m) x 64(n)
    const int warp_m = wid & 3;           // m offset 32*warp_m
    const int warp_n = wid >> 2;          // n offset 64*warp_n
    float acc[2][8][4];
#pragma unroll
    for (int mt = 0; mt < 2; mt++)
#pragma unroll
        for (int nt = 0; nt < 8; nt++)
#pragma unroll
            for (int q = 0; q < 4; q++) acc[mt][nt][q] = 0.f;

#pragma unroll 4
    for (int s = 0; s < 16; s++) {
        uint32_t a[2][4];
#pragma unroll
        for (int mt = 0; mt < 2; mt++) {
            const uint32_t* p = Af + ((warp_m * 2 + mt) * 16 + s) * A_BLK + lane * 4;
            uint4 v = *(const uint4*)p;
            a[mt][0] = v.x; a[mt][1] = v.y; a[mt][2] = v.z; a[mt][3] = v.w;
        }
        uint32_t b[8][2];
#pragma unroll
        for (int nt = 0; nt < 8; nt++) {
            const uint32_t* p = Bf + ((warp_n * 8 + nt) * 16 + s) * 64 + lane * 2;
            uint2 v = *(const uint2*)p;
            b[nt][0] = v.x; b[nt][1] = v.y;
        }
#pragma unroll
        for (int mt = 0; mt < 2; mt++)
#pragma unroll
            for (int nt = 0; nt < 8; nt++) {
                asm volatile(
                    "mma.sync.aligned.m16n8k8.row.col.f32.tf32.tf32.f32 "
                    "{%0,%1,%2,%3}, {%4,%5,%6,%7}, {%8,%9}, {%0,%1,%2,%3};"
                    : "+f"(acc[mt][nt][0]), "+f"(acc[mt][nt][1]),
                      "+f"(acc[mt][nt][2]), "+f"(acc[mt][nt][3])
                    : "r"(a[mt][0]), "r"(a[mt][1]), "r"(a[mt][2]), "r"(a[mt][3]),
                      "r"(b[nt][0]), "r"(b[nt][1]));
            }
    }

    // ---- epilogue
    const int g = lane >> 2, tg = lane & 3;
#pragma unroll
    for (int mt = 0; mt < 2; mt++)
#pragma unroll
        for (int hi = 0; hi < 2; hi++) {
            int grow = row0 + warp_m * 32 + mt * 16 + hi * 8 + g;
            if (grow < n_rows) {
                float* op = OUT + (size_t)grow * DD + warp_n * 64 + tg * 2;
#pragma unroll
                for (int nt = 0; nt < 8; nt++) {
                    float2 o;
                    o.x = acc[mt][nt][hi * 2 + 0];
                    o.y = acc[mt][nt][hi * 2 + 1];
                    *(float2*)(op + nt * 8) = o;
                }
            }
        }
}

__device__ __forceinline__ float lrelu(float x) {
    return x > 0.f ? x : 0.01f * x;
}

// ego = lrelu(S + b_s) + lrelu(P + b_p); out = ego / max(||ego||, 1e-12)
__global__ __launch_bounds__(256) void combine_norm_kernel(const float* __restrict__ bs,
                                                           const float* __restrict__ bp,
                                                           float* __restrict__ out_norm,
                                                           int n_rows) {
    int warp = (blockIdx.x * blockDim.x + threadIdx.x) >> 5;
    int lane = threadIdx.x & 31;
    if (warp >= n_rows) return;
    size_t off = (size_t)warp * DD + lane * 4;
    float4 s = *(const float4*)(g_S + off);
    float4 p = *(const float4*)(g_P + off);
    float4 b1 = *(const float4*)(bs + lane * 4);
    float4 b2 = *(const float4*)(bp + lane * 4);
    float4 e;
    e.x = lrelu(s.x + b1.x) + lrelu(p.x + b2.x);
    e.y = lrelu(s.y + b1.y) + lrelu(p.y + b2.y);
    e.z = lrelu(s.z + b1.z) + lrelu(p.z + b2.z);
    e.w = lrelu(s.w + b1.w) + lrelu(p.w + b2.w);
    float ss = e.x * e.x + e.y * e.y + e.z * e.z + e.w * e.w;
#pragma unroll
    for (int o = 16; o; o >>= 1) ss += __shfl_xor_sync(0xffffffffu, ss, o);
    float inv = 1.f / fmaxf(sqrtf(ss), 1e-12f);
    *(float4*)(g_ego + off) = e;
    float4 en;
    en.x = e.x * inv; en.y = e.y * inv; en.z = e.z * inv; en.w = e.w * inv;
    *(float4*)(out_norm + off) = en;
}

extern "C" void kernel_launch(void* const* d_in, const int* in_sizes, int n_in,
                              void* d_out, int out_size) {
    const float* emb    = (const float*)d_in[0];
    const int*   e_src  = (const int*)d_in[1];
    const int*   e_dst  = (const int*)d_in[2];
    const float* e_val  = (const float*)d_in[3];
    const float* W_sum  = (const float*)d_in[4];
    const float* b_sum  = (const float*)d_in[5];
    const float* W_prod = (const float*)d_in[6];
    const float* b_prod = (const float*)d_in[7];
    float* out = (float*)d_out;

    const int N = in_sizes[0] / DD;
    const int E = in_sizes[1];
    const int L = in_sizes[4] / (DD * DD);

    // Opt-in to >48KB dynamic smem. Config call, not a stream op — capture-safe.
    cudaFuncSetAttribute(gemm_mma_kernel,
                         cudaFuncAttributeMaxDynamicSharedMemorySize, GEMM_SMEM);

    const int n4 = N * (DD / 4);
    const int eb_blocks = (n4 + 255) / 256;

    copy_kernel<<<eb_blocks, 256>>>(emb, out, n4);

    const int spmm_blocks = (E + 7) / 8;
    const int gemm_bx = (N + 127) / 128;
    const int cn_blocks = (N + 7) / 8;

    for (int i = 0; i < L; i++) {
        const float* x = out + (size_t)i * N * DD;   // normalized prev layer
        zero_side_kernel<<<eb_blocks, 256>>>(n4);
        spmm_kernel<<<spmm_blocks, 256>>>(x, e_src, e_dst, e_val, E);
        gemm_mma_kernel<<<dim3(gemm_bx, 2), 256, GEMM_SMEM>>>(
            emb, (i == 0) ? 0 : 1,
            W_sum + (size_t)i * DD * DD, W_prod + (size_t)i * DD * DD, N);
        combine_norm_kernel<<<cn_blocks, 256>>>(b_sum + (size_t)i * DD,
                                                b_prod + (size_t)i * DD,
                                                out + (size_t)(i + 1) * N * DD, N);
    }
}

// round 9
// speedup vs baseline: 2.1070x; 1.3708x over previous
#include <cuda_runtime.h>
#include <cstdint>

#define NMAX 100000
#define DD 128

// Scratch (static device arrays; allocation is forbidden)
__device__ float g_side[(size_t)NMAX * DD];
__device__ float g_S[(size_t)NMAX * DD];
__device__ float g_P[(size_t)NMAX * DD];
__device__ float g_ego[(size_t)NMAX * DD];

__global__ __launch_bounds__(256) void copy_kernel(const float* __restrict__ src,
                                                   float* __restrict__ dst, int n4) {
    int i = blockIdx.x * blockDim.x + threadIdx.x;
    if (i < n4) ((float4*)dst)[i] = ((const float4*)src)[i];
}

__global__ __launch_bounds__(256) void zero_side_kernel(int n4) {
    int i = blockIdx.x * blockDim.x + threadIdx.x;
    if (i < n4) ((float4*)g_side)[i] = make_float4(0.f, 0.f, 0.f, 0.f);
}

// One warp per edge: gather src row, scale, v4-RED scatter-add to dst row.
__global__ __launch_bounds__(256) void spmm_kernel(const float* __restrict__ x,
                                                   const int* __restrict__ src,
                                                   const int* __restrict__ dst,
                                                   const float* __restrict__ val,
                                                   int E) {
    int warp = (blockIdx.x * blockDim.x + threadIdx.x) >> 5;
    int lane = threadIdx.x & 31;
    if (warp >= E) return;
    int s = __ldg(src + warp);
    int d = __ldg(dst + warp);
    float v = __ldg(val + warp);
    float4 m = ((const float4*)(x + (size_t)s * DD))[lane];
    float* o = g_side + (size_t)d * DD + lane * 4;
    asm volatile("red.global.add.v4.f32 [%0], {%1, %2, %3, %4};"
                 :: "l"(o), "f"(v * m.x), "f"(v * m.y), "f"(v * m.z), "f"(v * m.w)
                 : "memory");
}

// ---------------- tf32 mma.sync GEMM --------------------------------------
// OUT[n][j] = sum_k A[n][k] * W[k][j];  A = ego+side (mode 0 -> g_S) or
// ego*side (mode 1 -> g_P). 128x128x128 per CTA, 256 threads, 8 warps (4m x 2n),
// warp tile 32x64, mma.sync.m16n8k8 tf32.
// SMEM: plain row-major, XOR-swizzled, filled with LDG.128/STS.128:
//   As float4-index: row*32 + (col4 ^ (row & 7))
//   Bs float4-index: k  *32 + (col4 ^ ((k & 3) * 2))
// Both give conflict-free LDS.32 for the mma fragment gathers.
#define GEMM_SMEM (2 * 16384 * 4)       // A 64KB + B 64KB

__device__ __forceinline__ uint32_t to_tf32(float f) {
    uint32_t u;
    asm("cvt.rna.tf32.f32 %0, %1;" : "=r"(u) : "f"(f));
    return u;
}

__global__ __launch_bounds__(256, 1) void gemm_mma_kernel(const float* __restrict__ emb,
                                                          int use_g_ego,
                                                          const float* __restrict__ W_sum,
                                                          const float* __restrict__ W_prod,
                                                          int n_rows) {
    extern __shared__ uint32_t smem[];
    uint32_t* As = smem;                 // 16384 words
    uint32_t* Bs = smem + 16384;         // 16384 words

    const int tid = threadIdx.x;
    const int wid = tid >> 5;
    const int lane = tid & 31;
    const int mode = blockIdx.y;
    const int row0 = blockIdx.x * 128;

    const float* __restrict__ ego = use_g_ego ? (const float*)g_ego : emb;
    const float* __restrict__ W = mode ? W_prod : W_sum;
    float* __restrict__ OUT = mode ? g_P : g_S;

    // ---- fill: 16 passes, each pass = 8 rows x 32 float4-cols (fully coalesced)
    {
        const int col4 = tid & 31;
        const int rbase = tid >> 5;                 // 0..7 (== row & 7 every pass)
        const int a_sw = col4 ^ rbase;              // A swizzled float4 col
        const int b_sw = col4 ^ ((rbase & 3) << 1); // B swizzled float4 col
#pragma unroll
        for (int j = 0; j < 16; j++) {
            int row = j * 8 + rbase;
            int gr = row0 + row;
            float4 e = make_float4(0.f, 0.f, 0.f, 0.f), sd = e;
            if (gr < n_rows) {
                e = *(const float4*)(ego + (size_t)gr * DD + col4 * 4);
                sd = *(const float4*)(g_side + (size_t)gr * DD + col4 * 4);
            }
            float4 a;
            if (mode) { a.x = e.x * sd.x; a.y = e.y * sd.y; a.z = e.z * sd.z; a.w = e.w * sd.w; }
            else      { a.x = e.x + sd.x; a.y = e.y + sd.y; a.z = e.z + sd.z; a.w = e.w + sd.w; }
            uint4 ua = make_uint4(to_tf32(a.x), to_tf32(a.y), to_tf32(a.z), to_tf32(a.w));
            ((uint4*)As)[row * 32 + a_sw] = ua;

            float4 w = *(const float4*)(W + (size_t)row * DD + col4 * 4);  // row == k
            uint4 uw = make_uint4(to_tf32(w.x), to_tf32(w.y), to_tf32(w.z), to_tf32(w.w));
            ((uint4*)Bs)[row * 32 + b_sw] = uw;
        }
    }
    __syncthreads();

    // ---- compute: warp tile 32(m) x 64(n)
    const int warp_m = wid & 3;
    const int warp_n = wid >> 2;
    const int g = lane >> 2, tg = lane & 3;
    float acc[2][8][4];
#pragma unroll
    for (int mt = 0; mt < 2; mt++)
#pragma unroll
        for (int nt = 0; nt < 8; nt++)
#pragma unroll
            for (int q = 0; q < 4; q++) acc[mt][nt][q] = 0.f;

#pragma unroll 4
    for (int s = 0; s < 16; s++) {
        const int c4 = s * 2;
        uint32_t a[2][4];
#pragma unroll
        for (int mt = 0; mt < 2; mt++) {
            int r0 = warp_m * 32 + mt * 16 + g;          // r0 & 7 == g
            const uint32_t* lo = As + r0 * 128 + tg;
            const uint32_t* hi = As + (r0 + 8) * 128 + tg;
            a[mt][0] = lo[(c4 ^ g) * 4];
            a[mt][1] = hi[(c4 ^ g) * 4];
            a[mt][2] = lo[((c4 + 1) ^ g) * 4];
            a[mt][3] = hi[((c4 + 1) ^ g) * 4];
        }
        uint32_t b[8][2];
        const int k0 = s * 8 + tg;                       // k0 & 3 == tg
        const int sw = tg << 1;
        const uint32_t* b0p = Bs + k0 * 128;
        const uint32_t* b1p = Bs + (k0 + 4) * 128;       // (k0+4) & 3 == tg too
#pragma unroll
        for (int nt = 0; nt < 8; nt++) {
            int n = warp_n * 64 + nt * 8 + g;
            int idx = ((n >> 2) ^ sw) * 4 + (n & 3);
            b[nt][0] = b0p[idx];
            b[nt][1] = b1p[idx];
        }
#pragma unroll
        for (int mt = 0; mt < 2; mt++)
#pragma unroll
            for (int nt = 0; nt < 8; nt++) {
                asm volatile(
                    "mma.sync.aligned.m16n8k8.row.col.f32.tf32.tf32.f32 "
                    "{%0,%1,%2,%3}, {%4,%5,%6,%7}, {%8,%9}, {%0,%1,%2,%3};"
                    : "+f"(acc[mt][nt][0]), "+f"(acc[mt][nt][1]),
                      "+f"(acc[mt][nt][2]), "+f"(acc[mt][nt][3])
                    : "r"(a[mt][0]), "r"(a[mt][1]), "r"(a[mt][2]), "r"(a[mt][3]),
                      "r"(b[nt][0]), "r"(b[nt][1]));
            }
    }

    // ---- epilogue
#pragma unroll
    for (int mt = 0; mt < 2; mt++)
#pragma unroll
        for (int hi = 0; hi < 2; hi++) {
            int grow = row0 + warp_m * 32 + mt * 16 + hi * 8 + g;
            if (grow < n_rows) {
                float* op = OUT + (size_t)grow * DD + warp_n * 64 + tg * 2;
#pragma unroll
                for (int nt = 0; nt < 8; nt++) {
                    float2 o;
                    o.x = acc[mt][nt][hi * 2 + 0];
                    o.y = acc[mt][nt][hi * 2 + 1];
                    *(float2*)(op + nt * 8) = o;
                }
            }
        }
}

__device__ __forceinline__ float lrelu(float x) {
    return x > 0.f ? x : 0.01f * x;
}

// ego = lrelu(S + b_s) + lrelu(P + b_p); out = ego / max(||ego||, 1e-12)
__global__ __launch_bounds__(256) void combine_norm_kernel(const float* __restrict__ bs,
                                                           const float* __restrict__ bp,
                                                           float* __restrict__ out_norm,
                                                           int n_rows) {
    int warp = (blockIdx.x * blockDim.x + threadIdx.x) >> 5;
    int lane = threadIdx.x & 31;
    if (warp >= n_rows) return;
    size_t off = (size_t)warp * DD + lane * 4;
    float4 s = *(const float4*)(g_S + off);
    float4 p = *(const float4*)(g_P + off);
    float4 b1 = *(const float4*)(bs + lane * 4);
    float4 b2 = *(const float4*)(bp + lane * 4);
    float4 e;
    e.x = lrelu(s.x + b1.x) + lrelu(p.x + b2.x);
    e.y = lrelu(s.y + b1.y) + lrelu(p.y + b2.y);
    e.z = lrelu(s.z + b1.z) + lrelu(p.z + b2.z);
    e.w = lrelu(s.w + b1.w) + lrelu(p.w + b2.w);
    float ss = e.x * e.x + e.y * e.y + e.z * e.z + e.w * e.w;
#pragma unroll
    for (int o = 16; o; o >>= 1) ss += __shfl_xor_sync(0xffffffffu, ss, o);
    float inv = 1.f / fmaxf(sqrtf(ss), 1e-12f);
    *(float4*)(g_ego + off) = e;
    float4 en;
    en.x = e.x * inv; en.y = e.y * inv; en.z = e.z * inv; en.w = e.w * inv;
    *(float4*)(out_norm + off) = en;
}

extern "C" void kernel_launch(void* const* d_in, const int* in_sizes, int n_in,
                              void* d_out, int out_size) {
    const float* emb    = (const float*)d_in[0];
    const int*   e_src  = (const int*)d_in[1];
    const int*   e_dst  = (const int*)d_in[2];
    const float* e_val  = (const float*)d_in[3];
    const float* W_sum  = (const float*)d_in[4];
    const float* b_sum  = (const float*)d_in[5];
    const float* W_prod = (const float*)d_in[6];
    const float* b_prod = (const float*)d_in[7];
    float* out = (float*)d_out;

    const int N = in_sizes[0] / DD;
    const int E = in_sizes[1];
    const int L = in_sizes[4] / (DD * DD);

    // Opt-in to >48KB dynamic smem. Config call, not a stream op — capture-safe.
    cudaFuncSetAttribute(gemm_mma_kernel,
                         cudaFuncAttributeMaxDynamicSharedMemorySize, GEMM_SMEM);

    const int n4 = N * (DD / 4);
    const int eb_blocks = (n4 + 255) / 256;

    copy_kernel<<<eb_blocks, 256>>>(emb, out, n4);

    const int spmm_blocks = (E + 7) / 8;
    const int gemm_bx = (N + 127) / 128;
    const int cn_blocks = (N + 7) / 8;

    for (int i = 0; i < L; i++) {
        const float* x = out + (size_t)i * N * DD;   // normalized prev layer
        zero_side_kernel<<<eb_blocks, 256>>>(n4);
        spmm_kernel<<<spmm_blocks, 256>>>(x, e_src, e_dst, e_val, E);
        gemm_mma_kernel<<<dim3(gemm_bx, 2), 256, GEMM_SMEM>>>(
            emb, (i == 0) ? 0 : 1,
            W_sum + (size_t)i * DD * DD, W_prod + (size_t)i * DD * DD, N);
        combine_norm_kernel<<<cn_blocks, 256>>>(b_sum + (size_t)i * DD,
                                                b_prod + (size_t)i * DD,
                                                out + (size_t)(i + 1) * N * DD, N);
    }
}

// round 11
// speedup vs baseline: 3.2027x; 1.5200x over previous
#include <cuda_runtime.h>
#include <cstdint>

#define NMAX 100000
#define EMAX 1600000
#define DD 128
#define NB_SCAN 391            // ceil(NMAX/256)

// Scratch (static device arrays; allocation is forbidden)
__device__ float g_side[(size_t)NMAX * DD];
__device__ float g_S[(size_t)NMAX * DD];
__device__ float g_P[(size_t)NMAX * DD];
__device__ float g_ego[(size_t)NMAX * DD];
__device__ int g_deg[NMAX];
__device__ int g_off[NMAX];
__device__ int g_cur[NMAX];
__device__ int g_blk[512];
__device__ int g_eidx[EMAX];

__global__ __launch_bounds__(256) void copy_kernel(const float* __restrict__ src,
                                                   float* __restrict__ dst, int n4) {
    int i = blockIdx.x * blockDim.x + threadIdx.x;
    if (i < n4) ((float4*)dst)[i] = ((const float4*)src)[i];
}

// ------------------------- CSR build (per capture, reused by both layers)
__global__ __launch_bounds__(256) void zero_deg_kernel(int n) {
    int i = blockIdx.x * blockDim.x + threadIdx.x;
    if (i < n) g_deg[i] = 0;
}

__global__ __launch_bounds__(256) void hist_kernel(const int* __restrict__ dst, int E) {
    int i = blockIdx.x * blockDim.x + threadIdx.x;
    if (i < E) atomicAdd(&g_deg[__ldg(dst + i)], 1);
}

// per-block exclusive scan of deg -> g_off (block-local), block total -> g_blk
__global__ __launch_bounds__(256) void scan_part_kernel(int n) {
    __shared__ int sh[256];
    int i = blockIdx.x * 256 + threadIdx.x;
    int v = (i < n) ? g_deg[i] : 0;
    sh[threadIdx.x] = v;
    __syncthreads();
    int incl = v;
#pragma unroll
    for (int o = 1; o < 256; o <<= 1) {
        int t = (threadIdx.x >= o) ? sh[threadIdx.x - o] : 0;
        __syncthreads();
        incl += t;
        sh[threadIdx.x] = incl;
        __syncthreads();
    }
    if (i < n) g_off[i] = incl - v;
    if (threadIdx.x == 255) g_blk[blockIdx.x] = incl;
}

// single block: exclusive scan of g_blk[0..nb)
__global__ __launch_bounds__(512) void scan_blk_kernel(int nb) {
    __shared__ int sh[512];
    int t = threadIdx.x;
    int v = (t < nb) ? g_blk[t] : 0;
    sh[t] = v;
    __syncthreads();
    int incl = v;
#pragma unroll
    for (int o = 1; o < 512; o <<= 1) {
        int x = (t >= o) ? sh[t - o] : 0;
        __syncthreads();
        incl += x;
        sh[t] = incl;
        __syncthreads();
    }
    if (t < nb) g_blk[t] = incl - v;
}

__global__ __launch_bounds__(256) void scan_add_kernel(int n) {
    int i = blockIdx.x * 256 + threadIdx.x;
    if (i < n) {
        int o = g_off[i] + g_blk[blockIdx.x];
        g_off[i] = o;
        g_cur[i] = o;
    }
}

__global__ __launch_bounds__(256) void scatter_kernel(const int* __restrict__ dst, int E) {
    int i = blockIdx.x * blockDim.x + threadIdx.x;
    if (i < E) {
        int pos = atomicAdd(&g_cur[__ldg(dst + i)], 1);
        g_eidx[pos] = i;
    }
}

// ------------------------- CSR SpMM: one warp per dst row, register acc.
// Also replaces zero_side (deg-0 rows store zeros).
__global__ __launch_bounds__(256) void spmm_csr_kernel(const float* __restrict__ x,
                                                       const int* __restrict__ src,
                                                       const float* __restrict__ val,
                                                       int N) {
    int row = (blockIdx.x * blockDim.x + threadIdx.x) >> 5;
    int lane = threadIdx.x & 31;
    if (row >= N) return;
    int off = g_off[row];
    int deg = g_deg[row];
    float4 acc = make_float4(0.f, 0.f, 0.f, 0.f);
    for (int j0 = 0; j0 < deg; j0 += 32) {
        int myj = j0 + lane;
        int e = (myj < deg) ? __ldg(g_eidx + off + myj) : 0;
        int s = __ldg(src + e);
        float v = (myj < deg) ? __ldg(val + e) : 0.f;
        int cnt = min(32, deg - j0);
        int t = 0;
        for (; t + 1 < cnt; t += 2) {
            int s0 = __shfl_sync(0xffffffffu, s, t);
            int s1 = __shfl_sync(0xffffffffu, s, t + 1);
            float v0 = __shfl_sync(0xffffffffu, v, t);
            float v1 = __shfl_sync(0xffffffffu, v, t + 1);
            float4 m0 = ((const float4*)(x + (size_t)s0 * DD))[lane];
            float4 m1 = ((const float4*)(x + (size_t)s1 * DD))[lane];
            acc.x += v0 * m0.x; acc.y += v0 * m0.y;
            acc.z += v0 * m0.z; acc.w += v0 * m0.w;
            acc.x += v1 * m1.x; acc.y += v1 * m1.y;
            acc.z += v1 * m1.z; acc.w += v1 * m1.w;
        }
        if (t < cnt) {
            int s0 = __shfl_sync(0xffffffffu, s, t);
            float v0 = __shfl_sync(0xffffffffu, v, t);
            float4 m0 = ((const float4*)(x + (size_t)s0 * DD))[lane];
            acc.x += v0 * m0.x; acc.y += v0 * m0.y;
            acc.z += v0 * m0.z; acc.w += v0 * m0.w;
        }
    }
    ((float4*)(g_side + (size_t)row * DD))[lane] = acc;
}

// ---------------- tf32 mma.sync GEMM (unchanged from R9) ------------------
#define GEMM_SMEM (2 * 16384 * 4)       // A 64KB + B 64KB

__device__ __forceinline__ uint32_t to_tf32(float f) {
    uint32_t u;
    asm("cvt.rna.tf32.f32 %0, %1;" : "=r"(u) : "f"(f));
    return u;
}

__global__ __launch_bounds__(256, 1) void gemm_mma_kernel(const float* __restrict__ emb,
                                                          int use_g_ego,
                                                          const float* __restrict__ W_sum,
                                                          const float* __restrict__ W_prod,
                                                          int n_rows) {
    extern __shared__ uint32_t smem[];
    uint32_t* As = smem;                 // 16384 words
    uint32_t* Bs = smem + 16384;         // 16384 words

    const int tid = threadIdx.x;
    const int wid = tid >> 5;
    const int lane = tid & 31;
    const int mode = blockIdx.y;
    const int row0 = blockIdx.x * 128;

    const float* __restrict__ ego = use_g_ego ? (const float*)g_ego : emb;
    const float* __restrict__ W = mode ? W_prod : W_sum;
    float* __restrict__ OUT = mode ? g_P : g_S;

    // ---- fill: 16 passes, each pass = 8 rows x 32 float4-cols (coalesced)
    {
        const int col4 = tid & 31;
        const int rbase = tid >> 5;                 // 0..7 (== row & 7 every pass)
        const int a_sw = col4 ^ rbase;
        const int b_sw = col4 ^ ((rbase & 3) << 1);
#pragma unroll
        for (int j = 0; j < 16; j++) {
            int row = j * 8 + rbase;
            int gr = row0 + row;
            float4 e = make_float4(0.f, 0.f, 0.f, 0.f), sd = e;
            if (gr < n_rows) {
                e = *(const float4*)(ego + (size_t)gr * DD + col4 * 4);
                sd = *(const float4*)(g_side + (size_t)gr * DD + col4 * 4);
            }
            float4 a;
            if (mode) { a.x = e.x * sd.x; a.y = e.y * sd.y; a.z = e.z * sd.z; a.w = e.w * sd.w; }
            else      { a.x = e.x + sd.x; a.y = e.y + sd.y; a.z = e.z + sd.z; a.w = e.w + sd.w; }
            uint4 ua = make_uint4(to_tf32(a.x), to_tf32(a.y), to_tf32(a.z), to_tf32(a.w));
            ((uint4*)As)[row * 32 + a_sw] = ua;

            float4 w = *(const float4*)(W + (size_t)row * DD + col4 * 4);  // row == k
            uint4 uw = make_uint4(to_tf32(w.x), to_tf32(w.y), to_tf32(w.z), to_tf32(w.w));
            ((uint4*)Bs)[row * 32 + b_sw] = uw;
        }
    }
    __syncthreads();

    // ---- compute: warp tile 32(m) x 64(n)
    const int warp_m = wid & 3;
    const int warp_n = wid >> 2;
    const int g = lane >> 2, tg = lane & 3;
    float acc[2][8][4];
#pragma unroll
    for (int mt = 0; mt < 2; mt++)
#pragma unroll
        for (int nt = 0; nt < 8; nt++)
#pragma unroll
            for (int q = 0; q < 4; q++) acc[mt][nt][q] = 0.f;

#pragma unroll 4
    for (int s = 0; s < 16; s++) {
        const int c4 = s * 2;
        uint32_t a[2][4];
#pragma unroll
        for (int mt = 0; mt < 2; mt++) {
            int r0 = warp_m * 32 + mt * 16 + g;          // r0 & 7 == g
            const uint32_t* lo = As + r0 * 128 + tg;
            const uint32_t* hi = As + (r0 + 8) * 128 + tg;
            a[mt][0] = lo[(c4 ^ g) * 4];
            a[mt][1] = hi[(c4 ^ g) * 4];
            a[mt][2] = lo[((c4 + 1) ^ g) * 4];
            a[mt][3] = hi[((c4 + 1) ^ g) * 4];
        }
        uint32_t b[8][2];
        const int k0 = s * 8 + tg;                       // k0 & 3 == tg
        const int sw = tg << 1;
        const uint32_t* b0p = Bs + k0 * 128;
        const uint32_t* b1p = Bs + (k0 + 4) * 128;
#pragma unroll
        for (int nt = 0; nt < 8; nt++) {
            int n = warp_n * 64 + nt * 8 + g;
            int idx = ((n >> 2) ^ sw) * 4 + (n & 3);
            b[nt][0] = b0p[idx];
            b[nt][1] = b1p[idx];
        }
#pragma unroll
        for (int mt = 0; mt < 2; mt++)
#pragma unroll
            for (int nt = 0; nt < 8; nt++) {
                asm volatile(
                    "mma.sync.aligned.m16n8k8.row.col.f32.tf32.tf32.f32 "
                    "{%0,%1,%2,%3}, {%4,%5,%6,%7}, {%8,%9}, {%0,%1,%2,%3};"
                    : "+f"(acc[mt][nt][0]), "+f"(acc[mt][nt][1]),
                      "+f"(acc[mt][nt][2]), "+f"(acc[mt][nt][3])
                    : "r"(a[mt][0]), "r"(a[mt][1]), "r"(a[mt][2]), "r"(a[mt][3]),
                      "r"(b[nt][0]), "r"(b[nt][1]));
            }
    }

    // ---- epilogue
#pragma unroll
    for (int mt = 0; mt < 2; mt++)
#pragma unroll
        for (int hi = 0; hi < 2; hi++) {
            int grow = row0 + warp_m * 32 + mt * 16 + hi * 8 + g;
            if (grow < n_rows) {
                float* op = OUT + (size_t)grow * DD + warp_n * 64 + tg * 2;
#pragma unroll
                for (int nt = 0; nt < 8; nt++) {
                    float2 o;
                    o.x = acc[mt][nt][hi * 2 + 0];
                    o.y = acc[mt][nt][hi * 2 + 1];
                    *(float2*)(op + nt * 8) = o;
                }
            }
        }
}

__device__ __forceinline__ float lrelu(float x) {
    return x > 0.f ? x : 0.01f * x;
}

// ego = lrelu(S + b_s) + lrelu(P + b_p); out = ego / max(||ego||, 1e-12)
__global__ __launch_bounds__(256) void combine_norm_kernel(const float* __restrict__ bs,
                                                           const float* __restrict__ bp,
                                                           float* __restrict__ out_norm,
                                                           int n_rows) {
    int warp = (blockIdx.x * blockDim.x + threadIdx.x) >> 5;
    int lane = threadIdx.x & 31;
    if (warp >= n_rows) return;
    size_t off = (size_t)warp * DD + lane * 4;
    float4 s = *(const float4*)(g_S + off);
    float4 p = *(const float4*)(g_P + off);
    float4 b1 = *(const float4*)(bs + lane * 4);
    float4 b2 = *(const float4*)(bp + lane * 4);
    float4 e;
    e.x = lrelu(s.x + b1.x) + lrelu(p.x + b2.x);
    e.y = lrelu(s.y + b1.y) + lrelu(p.y + b2.y);
    e.z = lrelu(s.z + b1.z) + lrelu(p.z + b2.z);
    e.w = lrelu(s.w + b1.w) + lrelu(p.w + b2.w);
    float ss = e.x * e.x + e.y * e.y + e.z * e.z + e.w * e.w;
#pragma unroll
    for (int o = 16; o; o >>= 1) ss += __shfl_xor_sync(0xffffffffu, ss, o);
    float inv = 1.f / fmaxf(sqrtf(ss), 1e-12f);
    *(float4*)(g_ego + off) = e;
    float4 en;
    en.x = e.x * inv; en.y = e.y * inv; en.z = e.z * inv; en.w = e.w * inv;
    *(float4*)(out_norm + off) = en;
}

extern "C" void kernel_launch(void* const* d_in, const int* in_sizes, int n_in,
                              void* d_out, int out_size) {
    const float* emb    = (const float*)d_in[0];
    const int*   e_src  = (const int*)d_in[1];
    const int*   e_dst  = (const int*)d_in[2];
    const float* e_val  = (const float*)d_in[3];
    const float* W_sum  = (const float*)d_in[4];
    const float* b_sum  = (const float*)d_in[5];
    const float* W_prod = (const float*)d_in[6];
    const float* b_prod = (const float*)d_in[7];
    float* out = (float*)d_out;

    const int N = in_sizes[0] / DD;
    const int E = in_sizes[1];
    const int L = in_sizes[4] / (DD * DD);

    cudaFuncSetAttribute(gemm_mma_kernel,
                         cudaFuncAttributeMaxDynamicSharedMemorySize, GEMM_SMEM);

    const int n4 = N * (DD / 4);
    const int eb_blocks = (n4 + 255) / 256;
    const int nblocks = (N + 255) / 256;
    const int eblocks = (E + 255) / 256;

    copy_kernel<<<eb_blocks, 256>>>(emb, out, n4);

    // CSR build (once per launch, reused by both layers)
    zero_deg_kernel<<<nblocks, 256>>>(N);
    hist_kernel<<<eblocks, 256>>>(e_dst, E);
    scan_part_kernel<<<nblocks, 256>>>(N);
    scan_blk_kernel<<<1, 512>>>(nblocks);
    scan_add_kernel<<<nblocks, 256>>>(N);
    scatter_kernel<<<eblocks, 256>>>(e_dst, E);

    const int spmm_blocks = (N + 7) / 8;          // 1 warp/row, 8 warps/block
    const int gemm_bx = (N + 127) / 128;
    const int cn_blocks = (N + 7) / 8;

    for (int i = 0; i < L; i++) {
        const float* x = out + (size_t)i * N * DD;   // normalized prev layer
        spmm_csr_kernel<<<spmm_blocks, 256>>>(x, e_src, e_val, N);
        gemm_mma_kernel<<<dim3(gemm_bx, 2), 256, GEMM_SMEM>>>(
            emb, (i == 0) ? 0 : 1,
            W_sum + (size_t)i * DD * DD, W_prod + (size_t)i * DD * DD, N);
        combine_norm_kernel<<<cn_blocks, 256>>>(b_sum + (size_t)i * DD,
                                                b_prod + (size_t)i * DD,
                                                out + (size_t)(i + 1) * N * DD, N);
    }
}